// round 17
// baseline (speedup 1.0000x reference)
#include <cuda_runtime.h>

#define B_   256
#define M_   8
#define L_   64
#define E_   128
#define H_   8
#define HD_  16
#define QKV_ 384
#define QP_  392          // padded qkv row stride in smem
#define R_   (B_ * M_)    // 2048 rows

// Scratch (no allocation allowed -> __device__ globals)
__device__ float g_agg0[R_ * E_];        // mean-fused walk aggregate, row = b*8+m
__device__ float g_agg1[R_ * E_];        // after per-metapath linear, row = b*8+m
__device__ float g_WqkvT[E_ * QKV_];     // Wqkv transposed: [e][j]
__device__ float g_WoT[E_ * E_];         // Wo transposed:   [e][j]

// ---------------------------------------------------------------------------
// Kernel A: gather + elementwise fuse + mean over walk steps (VECTORIZED).
// block = (b*M + m); 512 threads = (e-group eg in [0,32)) x (sixteenth q).
// Each thread: 4 walk steps x 3 LDG.128.  Partials reduced via smem.
// Folds the weight transposes (32 elements/block).
// ---------------------------------------------------------------------------
__global__ void __launch_bounds__(512) k_gather(const int*   __restrict__ walks,
                                                const float* __restrict__ node_table,
                                                const float* __restrict__ fc1_b,
                                                const float* __restrict__ edge_table,
                                                const float* __restrict__ Wqkv,
                                                const float* __restrict__ Wo) {
    __shared__ int    s_idx[L_ * 3];
    __shared__ __align__(16) float4 s_part4[16][32];   // [q][eg], 8 KB
    const int bid = blockIdx.x;
    const int tid = threadIdx.x;
    const int eg  = tid & 31;          // float4 index within row
    const int q   = tid >> 5;          // walk sixteenth 0..15

    // folded transpose: 32 elements per block (2048 blocks x 32 = 65536)
    if (tid < 32) {
        int idx = bid * 32 + tid;
        if (idx < E_ * QKV_) {
            int j = idx / E_;
            int ee = idx % E_;
            g_WqkvT[ee * QKV_ + j] = Wqkv[idx];
        } else {
            int k2 = idx - E_ * QKV_;
            int j = k2 / E_;
            int ee = k2 % E_;
            g_WoT[ee * E_ + j] = Wo[k2];
        }
    }

    const int base = bid * (L_ * 3);
    for (int i = tid; i < L_ * 3; i += 512) s_idx[i] = walks[base + i];
    __syncthreads();

    const float4* nt4 = reinterpret_cast<const float4*>(node_table);
    const float4* et4 = reinterpret_cast<const float4*>(edge_table);
    const float4 fb = reinterpret_cast<const float4*>(fc1_b)[eg];

    float4 acc = make_float4(0.f, 0.f, 0.f, 0.f);
    const int l0 = q * 4;
#pragma unroll
    for (int l = l0; l < l0 + 4; l++) {
        int n1 = s_idx[3 * l + 0];
        int n2 = s_idx[3 * l + 1];
        int et = s_idx[3 * l + 2];
        float4 a = nt4[n1 * 32 + eg];
        float4 b = nt4[n2 * 32 + eg];
        float4 c = et4[et * 32 + eg];
        acc.x += (a.x + fb.x) * (b.x + fb.x) * c.x;
        acc.y += (a.y + fb.y) * (b.y + fb.y) * c.y;
        acc.z += (a.z + fb.z) * (b.z + fb.z) * c.z;
        acc.w += (a.w + fb.w) * (b.w + fb.w) * c.w;
    }
    s_part4[q][eg] = acc;
    __syncthreads();

    // reduce 16 partials per e; threads 0..127, one per e
    if (tid < E_) {
        const int eg2 = tid >> 2;
        const int cc  = tid & 3;
        float s = 0.f;
#pragma unroll
        for (int qq = 0; qq < 16; qq++) {
            const float* p = reinterpret_cast<const float*>(&s_part4[qq][eg2]);
            s += p[cc];
        }
        g_agg0[bid * E_ + tid] = s * (1.f / (float)L_);
    }
}

// ---------------------------------------------------------------------------
// Kernel B: per-metapath linear.  block = (m, 8-batch tile); 512 threads =
// 128 cols x 4 rowgroups of 2 rows.  grid = 8 x 32 = 256 blocks x 16 warps
// (same chip-wide warp count as the 4-batch version, half the weight traffic).
// ---------------------------------------------------------------------------
__global__ void __launch_bounds__(512) k_mplinear(const int*   __restrict__ mp_type_idx,
                                                  const float* __restrict__ W_mp,
                                                  const float* __restrict__ b_mp) {
    __shared__ __align__(16) float s_xT[E_][8];
    const int m   = blockIdx.x;
    const int b0  = blockIdx.y * 8;
    const int tid = threadIdx.x;
    const int j   = tid & 127;
    const int rg  = tid >> 7;          // 0..3 -> rows rg*2, rg*2+1

    for (int i = tid; i < 8 * E_; i += 512) {
        int row = i >> 7;
        int e   = i & 127;
        s_xT[e][row] = g_agg0[((b0 + row) * M_ + m) * E_ + e];
    }
    __syncthreads();

    const int mt = mp_type_idx[m];
    const float* W = W_mp + mt * (E_ * E_);
    const float bv = b_mp[mt * E_ + j];

    float acc0 = bv, acc1 = bv;

#pragma unroll 2
    for (int ee = 0; ee < E_; ee += 8) {
        float w[8];
#pragma unroll
        for (int u = 0; u < 8; u++) w[u] = W[(ee + u) * E_ + j];
#pragma unroll
        for (int u = 0; u < 8; u++) {
            float2 x = *reinterpret_cast<const float2*>(&s_xT[ee + u][rg * 2]);
            acc0 += x.x * w[u];
            acc1 += x.y * w[u];
        }
    }
    g_agg1[((b0 + rg * 2 + 0) * M_ + m) * E_ + j] = acc0;
    g_agg1[((b0 + rg * 2 + 1) * M_ + m) * E_ + j] = acc1;
}

// ---------------------------------------------------------------------------
// Kernel CD: fused QKV + attention core + output projection.
// TWO batches per block (rows b0*8 .. b0*8+15 of g_agg1, contiguous);
// 768 threads; grid 128.  Second batch's weight stream hits L1.
// ---------------------------------------------------------------------------
__global__ void __launch_bounds__(768) k_qkvattn(const float* __restrict__ bqkv,
                                                 const float* __restrict__ bo,
                                                 float* __restrict__ out) {
    __shared__ __align__(16) float s_xT[E_][16];      // x transposed [e][row], 8 KB
    __shared__ __align__(16) float s_q[2][M_][QP_];   // qkv rows, 25 KB
    __shared__ __align__(16) float s_oT[E_][16];      // attn out transposed, 8 KB

    const int tid = threadIdx.x;
    const int b0  = blockIdx.x * 2;

    // ---- stage x transposed (rows b0*8 .. b0*8+15 are contiguous, 8 KB) ----
    for (int i = tid; i < 16 * E_; i += 768) {
        int row = i >> 7;           // 0..15:  bb = row>>3, m = row&7
        int e   = i & 127;
        s_xT[e][row] = g_agg1[b0 * (M_ * E_) + i];
    }
    __syncthreads();

    // ---- QKV: 768 thr = 384 cols x 2 batchgroups; 8 rows (one batch) each ----
    {
        const int c  = (tid < 384) ? tid : (tid - 384);
        const int bg = (tid < 384) ? 0 : 1;      // batch group
        const int r0 = bg * 8;                   // rows r0 .. r0+7 of s_xT
        const float bv = bqkv[c];
        float acc[8] = {bv, bv, bv, bv, bv, bv, bv, bv};

#pragma unroll 2
        for (int ee = 0; ee < E_; ee += 8) {
            float w[8];
#pragma unroll
            for (int u = 0; u < 8; u++) w[u] = g_WqkvT[(ee + u) * QKV_ + c];
#pragma unroll
            for (int u = 0; u < 8; u++) {
                float4 x0 = *reinterpret_cast<const float4*>(&s_xT[ee + u][r0 + 0]);
                float4 x1 = *reinterpret_cast<const float4*>(&s_xT[ee + u][r0 + 4]);
                acc[0] += x0.x * w[u]; acc[1] += x0.y * w[u];
                acc[2] += x0.z * w[u]; acc[3] += x0.w * w[u];
                acc[4] += x1.x * w[u]; acc[5] += x1.y * w[u];
                acc[6] += x1.z * w[u]; acc[7] += x1.w * w[u];
            }
        }
#pragma unroll
        for (int i = 0; i < 8; i++) s_q[bg][i][c] = acc[i];
    }
    __syncthreads();

    // ---- attention core: one thread per (bb, h, m); 128 threads ----
    if (tid < 2 * H_ * M_) {
        const int bb = tid >> 6;
        const int h  = (tid >> 3) & 7;
        const int mm = tid & 7;
        const int hb = h * HD_;

        float4 q0 = *reinterpret_cast<const float4*>(&s_q[bb][mm][hb + 0]);
        float4 q1 = *reinterpret_cast<const float4*>(&s_q[bb][mm][hb + 4]);
        float4 q2 = *reinterpret_cast<const float4*>(&s_q[bb][mm][hb + 8]);
        float4 q3 = *reinterpret_cast<const float4*>(&s_q[bb][mm][hb + 12]);

        float s[M_];
        float mx = -1e30f;
#pragma unroll
        for (int n = 0; n < M_; n++) {
            const float* kp = &s_q[bb][n][E_ + hb];
            float4 k0 = *reinterpret_cast<const float4*>(kp + 0);
            float4 k1 = *reinterpret_cast<const float4*>(kp + 4);
            float4 k2 = *reinterpret_cast<const float4*>(kp + 8);
            float4 k3 = *reinterpret_cast<const float4*>(kp + 12);
            float d = q0.x*k0.x + q0.y*k0.y + q0.z*k0.z + q0.w*k0.w
                    + q1.x*k1.x + q1.y*k1.y + q1.z*k1.z + q1.w*k1.w
                    + q2.x*k2.x + q2.y*k2.y + q2.z*k2.z + q2.w*k2.w
                    + q3.x*k3.x + q3.y*k3.y + q3.z*k3.z + q3.w*k3.w;
            s[n] = d * 0.25f;
            mx = fmaxf(mx, s[n]);
        }
        float sum = 0.f;
#pragma unroll
        for (int n = 0; n < M_; n++) { s[n] = __expf(s[n] - mx); sum += s[n]; }
        const float inv = 1.f / sum;

        float o[HD_];
#pragma unroll
        for (int t = 0; t < HD_; t++) o[t] = 0.f;
#pragma unroll
        for (int n = 0; n < M_; n++) {
            float p = s[n] * inv;
            const float* vp = &s_q[bb][n][2 * E_ + hb];
#pragma unroll
            for (int t = 0; t < HD_; t++) o[t] += p * vp[t];
        }
#pragma unroll
        for (int t = 0; t < HD_; t++) s_oT[hb + t][bb * 8 + mm] = o[t];
    }
    __syncthreads();

    // ---- output projection: 512 active thr = 128 cols x 4 rowgroups of 4 ----
    if (tid < 512) {
        const int j  = tid & 127;
        const int rg = tid >> 7;           // rows rg*4 .. rg*4+3 (of 16)
        const float bv = bo[j];
        float acc[4] = {bv, bv, bv, bv};

#pragma unroll 2
        for (int ee = 0; ee < E_; ee += 8) {
            float w[8];
#pragma unroll
            for (int u = 0; u < 8; u++) w[u] = g_WoT[(ee + u) * E_ + j];
#pragma unroll
            for (int u = 0; u < 8; u++) {
                float4 x = *reinterpret_cast<const float4*>(&s_oT[ee + u][rg * 4]);
                acc[0] += x.x * w[u];
                acc[1] += x.y * w[u];
                acc[2] += x.z * w[u];
                acc[3] += x.w * w[u];
            }
        }
#pragma unroll
        for (int i = 0; i < 4; i++) {
            int row = rg * 4 + i;          // 0..15
            int bb  = row >> 3;
            int m   = row & 7;
            out[m * (B_ * E_) + (b0 + bb) * E_ + j] = acc[i];
        }
    }
}

// ---------------------------------------------------------------------------
extern "C" void kernel_launch(void* const* d_in, const int* in_sizes, int n_in,
                              void* d_out, int out_size) {
    (void)in_sizes; (void)n_in; (void)out_size;
    const int*   node_idx    = (const int*)d_in[0];  (void)node_idx;
    const int*   mp_type_idx = (const int*)d_in[1];
    const int*   walks       = (const int*)d_in[2];
    const float* node_table  = (const float*)d_in[3];
    const float* fc1_b       = (const float*)d_in[4];
    const float* edge_table  = (const float*)d_in[5];
    const float* W_mp        = (const float*)d_in[6];
    const float* b_mp        = (const float*)d_in[7];
    const float* Wqkv        = (const float*)d_in[8];
    const float* bqkv        = (const float*)d_in[9];
    const float* Wo          = (const float*)d_in[10];
    const float* bo          = (const float*)d_in[11];
    float* out = (float*)d_out;

    k_gather<<<B_ * M_, 512>>>(walks, node_table, fc1_b, edge_table, Wqkv, Wo);
    dim3 gB(M_, B_ / 8);
    k_mplinear<<<gB, 512>>>(mp_type_idx, W_mp, b_mp);
    k_qkvattn<<<B_ / 2, 768>>>(bqkv, bo, out);
}